// round 14
// baseline (speedup 1.0000x reference)
#include <cuda_runtime.h>
#include <math.h>

#define BB   128
#define CCH  32
#define HW2  256     // 16*16
#define NE   4096
#define NTOT (BB*CCH*HW2)   // 1048576

// ---------------- device scratch (no allocations allowed) ----------------
__device__ float g_frest[NTOT];
__device__ float g_fhat[NTOT];
__device__ float g_x[BB*CCH*169];          // max downsampled (pn=13)
__device__ float g_h0[NTOT];               // codebook gather output
__device__ float g_hup[NTOT];              // upsampled h
__device__ __align__(16) float g_cbn[NE*CCH];
__device__ float g_pmax[140000];
__device__ int   g_pidx[140000];
__device__ int   g_idx[BB*256];
__device__ float g_losssum;
__device__ int   g_hist[NE];
__device__ float g_tw[9][16][4];
__device__ int   g_tj[9][16][4];
__device__ int   g_phik[10];               // device-computed phi schedule

__constant__ int c_pns9[9] = {1,2,3,4,5,6,8,10,13};

// ---------------- f32x2 helpers ----------------
__device__ __forceinline__ unsigned long long pack2f(float a, float b) {
    unsigned long long r;
    asm("mov.b64 %0, {%1, %2};" : "=l"(r) : "f"(a), "f"(b));
    return r;
}
__device__ __forceinline__ void fma2(unsigned long long& acc, unsigned long long a, unsigned long long b) {
    asm("fma.rn.f32x2 %0, %1, %2, %0;" : "+l"(acc) : "l"(a), "l"(b));
}
__device__ __forceinline__ void unpack2f(unsigned long long v, float& x, float& y) {
    asm("mov.b64 {%0, %1}, %2;" : "=f"(x), "=f"(y) : "l"(v));
}

// ---------------- init: bicubic taps + phi tick schedule ----------------
__global__ void k_taps() {
    int i = threadIdx.x;
    if (i == 0) {
        // Bit-exact replication of:
        //   ticks = np.linspace(1/12, 1-1/12, 4)
        //   PHI_IDX[si] = argmin |ticks - si/9|   (first min on ties)
        double start = 1.0 / 12.0;
        double stop  = 1.0 - 1.0 / 12.0;
        double step  = (stop - start) / 3.0;
        double ticks[4];
        ticks[0] = start;
        ticks[1] = 1.0 * step + start;
        ticks[2] = 2.0 * step + start;   // 2*step exact (pow2 mul) -> FMA-safe
        ticks[3] = stop;
        for (int si = 0; si < 10; si++) {
            double v = (double)si / 9.0;
            int k = 0;
            double bd = fabs(ticks[0] - v);
            for (int j = 1; j < 4; j++) {
                double d = fabs(ticks[j] - v);
                if (d < bd) { bd = d; k = j; }
            }
            g_phik[si] = k;
        }
    }
    if (i >= 144) return;
    int si = i / 16, oi = i % 16;
    int pn = c_pns9[si];
    double src = (oi + 0.5) * (double)pn / 16.0 - 0.5;
    double fl = floor(src);
    int i0 = (int)fl;
    double f = src - fl;
    const double a = -0.75;
    #pragma unroll
    for (int off = -1; off <= 2; off++) {
        double t = fabs(f - (double)off);
        double w;
        if (t <= 1.0)      w = ((a + 2.0) * t - (a + 3.0)) * t * t + 1.0;
        else if (t < 2.0)  w = (((t - 5.0) * t + 8.0) * t - 4.0) * a;
        else               w = 0.0;
        int j = i0 + off;
        if (j < 0) j = 0;
        if (j > pn - 1) j = pn - 1;
        g_tw[si][oi][off + 1] = (float)w;
        g_tj[si][oi][off + 1] = j;
    }
}

// ---------------- codebook row-normalize ----------------
__global__ void k_cbnorm(const float* __restrict__ cb) {
    int row  = blockIdx.x * 8 + (threadIdx.x >> 5);
    int lane = threadIdx.x & 31;
    float v = cb[row * CCH + lane];
    float ss = v * v;
    #pragma unroll
    for (int o = 16; o; o >>= 1) ss += __shfl_xor_sync(0xffffffffu, ss, o);
    float nrm = fmaxf(sqrtf(ss), 1e-12f);
    g_cbn[row * CCH + lane] = v / nrm;
}

// ---------------- area downsample (f_rest -> x) ----------------
__global__ void k_down(const float* __restrict__ in, float* __restrict__ out, int pn) {
    int e = blockIdx.x * 256 + threadIdx.x;
    int pp = pn * pn;
    int tot = BB * CCH * pp;
    if (e >= tot) return;
    int p  = e % pn;
    int o  = (e / pn) % pn;
    int bc = e / pp;
    int s0 = (o * 16) / pn,       e0 = ((o + 1) * 16 + pn - 1) / pn;
    int s1 = (p * 16) / pn,       e1 = ((p + 1) * 16 + pn - 1) / pn;
    const float* base = in + (size_t)bc * HW2;
    float sum = 0.f;
    for (int y = s0; y < e0; y++)
        for (int x = s1; x < e1; x++)
            sum += base[y * 16 + x];
    out[e] = sum / (float)((e0 - s0) * (e1 - s1));
}

// ---------------- cosine argmax (partial over a code slice) ----------------
__global__ void k_argmax(const float* __restrict__ x, int pp, int T, int cs) {
    __shared__ __align__(16) float sh[128 * 32];
    int slice  = blockIdx.y;
    int c0base = slice * cs;
    int t = blockIdx.x * 256 + threadIdx.x;
    bool valid = (t < T);
    unsigned long long xp[16];
    if (valid) {
        int b = t / pp, r = t - b * pp;
        const float* bp = x + (size_t)b * CCH * pp + r;
        #pragma unroll
        for (int q = 0; q < 16; q++)
            xp[q] = pack2f(bp[(2 * q) * pp], bp[(2 * q + 1) * pp]);
    }
    float best = -1e30f;
    int bi = 0;
    for (int tile = 0; tile < cs; tile += 128) {
        const float4* src = (const float4*)(g_cbn + (size_t)(c0base + tile) * CCH);
        float4* dst = (float4*)sh;
        #pragma unroll
        for (int q = 0; q < 4; q++)
            dst[threadIdx.x + q * 256] = src[threadIdx.x + q * 256];
        __syncthreads();
        if (valid) {
            #pragma unroll 4
            for (int c = 0; c < 128; c += 2) {
                const longlong2* r0 = (const longlong2*)(sh + c * 32);
                const longlong2* r1 = (const longlong2*)(sh + c * 32 + 32);
                unsigned long long a0 = 0ull, a1 = 0ull;
                #pragma unroll
                for (int q = 0; q < 8; q++) {
                    longlong2 v0 = r0[q];
                    longlong2 v1 = r1[q];
                    fma2(a0, xp[2 * q],     (unsigned long long)v0.x);
                    fma2(a0, xp[2 * q + 1], (unsigned long long)v0.y);
                    fma2(a1, xp[2 * q],     (unsigned long long)v1.x);
                    fma2(a1, xp[2 * q + 1], (unsigned long long)v1.y);
                }
                float s0x, s0y, s1x, s1y;
                unpack2f(a0, s0x, s0y);
                unpack2f(a1, s1x, s1y);
                float s0 = s0x + s0y, s1 = s1x + s1y;
                if (s0 > best) { best = s0; bi = c0base + tile + c; }
                if (s1 > best) { best = s1; bi = c0base + tile + c + 1; }
            }
        }
        __syncthreads();
    }
    if (valid) {
        g_pmax[(size_t)slice * T + t] = best;
        g_pidx[(size_t)slice * T + t] = bi;
    }
}

// ---------------- merge partials + gather codebook -> h0 ----------------
__global__ void k_merge(const float* __restrict__ cb, int pp, int T, int S, int last) {
    int e = blockIdx.x * 256 + threadIdx.x;
    if (e >= T * CCH) return;
    int r = e % pp;
    int c = (e / pp) & 31;
    int b = e / (CCH * pp);
    int t = b * pp + r;
    float best = -1e30f;
    int bi = 0;
    for (int s = 0; s < S; s++) {
        float v = g_pmax[(size_t)s * T + t];
        if (v > best) { best = v; bi = g_pidx[(size_t)s * T + t]; }
    }
    g_h0[e] = cb[bi * CCH + c];
    if (last && c == 0) g_idx[t] = bi;
}

// ---------------- bicubic upsample (h0 -> hup) ----------------
__global__ void k_up(int pn, int si) {
    int e = blockIdx.x * 256 + threadIdx.x;   // < NTOT
    int x = e & 15, y = (e >> 4) & 15, bc = e >> 8;
    const float* base = g_h0 + (size_t)bc * pn * pn;
    float acc = 0.f;
    #pragma unroll
    for (int a = 0; a < 4; a++) {
        int jy = g_tj[si][y][a];
        float wy = g_tw[si][y][a];
        float rs = 0.f;
        #pragma unroll
        for (int bq = 0; bq < 4; bq++)
            rs += g_tw[si][x][bq] * base[jy * pn + g_tj[si][x][bq]];
        acc += wy * rs;
    }
    g_hup[e] = acc;
}

// ---------------- fused conv3x3 + phi-blend + fhat/frest update + loss ----------------
__global__ void k_phi(const float* __restrict__ h, const float* __restrict__ pw,
                      const float* __restrict__ pb, const float* __restrict__ fin, int si) {
    extern __shared__ float sm[];
    float* s_in = sm;                 // 8192 floats
    float* s_w  = sm + 8192;          // 32*32*12 = 12288 floats (padded per (co,ci))
    float* s_b  = sm + 8192 + 12288;  // 32 floats
    __shared__ float s_red[256];
    int b = blockIdx.x, tid = threadIdx.x;
    int kphi = g_phik[si];

    const float* hb = h + (size_t)b * 8192;
    for (int i = tid; i < 8192; i += 256) s_in[i] = hb[i];
    const float* wb = pw + (size_t)kphi * 9216;
    for (int i = tid; i < 9216; i += 256) {
        int oc = i / 9, k = i - oc * 9;
        s_w[oc * 12 + k] = wb[i];
    }
    if (tid < 32) s_b[tid] = pb[kphi * 32 + tid];
    __syncthreads();

    int y = tid >> 4, x = tid & 15;
    float acc[32];
    #pragma unroll
    for (int co = 0; co < 32; co++) acc[co] = 0.f;

    #pragma unroll 1
    for (int ci = 0; ci < 32; ci++) {
        float n[9];
        #pragma unroll
        for (int ky = 0; ky < 3; ky++)
            #pragma unroll
            for (int kx = 0; kx < 3; kx++) {
                int yy = y + ky - 1, xx = x + kx - 1;
                n[ky * 3 + kx] = (yy >= 0 && yy < 16 && xx >= 0 && xx < 16)
                               ? s_in[ci * 256 + yy * 16 + xx] : 0.f;
            }
        #pragma unroll
        for (int co = 0; co < 32; co++) {
            const float* wp = s_w + (co * 32 + ci) * 12;
            float4 w0 = *(const float4*)wp;
            float4 w1 = *(const float4*)(wp + 4);
            float w8 = wp[8];
            acc[co] += n[0]*w0.x + n[1]*w0.y + n[2]*w0.z + n[3]*w0.w
                     + n[4]*w1.x + n[5]*w1.y + n[6]*w1.z + n[7]*w1.w + n[8]*w8;
        }
    }

    float ls = 0.f;
    size_t base = (size_t)b * 8192 + tid;
    #pragma unroll
    for (int co = 0; co < 32; co++) {
        size_t e = base + (size_t)co * 256;
        float hv = s_in[co * 256 + tid];
        float hp = 0.5f * hv + 0.5f * (acc[co] + s_b[co]);
        float fh = g_fhat[e] + hp;
        g_fhat[e] = fh;
        g_frest[e] = g_frest[e] - hp;
        float d = fh - fin[e];
        ls += d * d;
    }
    s_red[tid] = ls;
    __syncthreads();
    for (int o = 128; o; o >>= 1) {
        if (tid < o) s_red[tid] += s_red[tid + o];
        __syncthreads();
    }
    if (tid == 0) atomicAdd(&g_losssum, s_red[0]);
}

// ---------------- histogram of last-scale indices ----------------
__global__ void k_hist() {
    int e = blockIdx.x * 256 + threadIdx.x;
    if (e < BB * 256) atomicAdd(&g_hist[g_idx[e]], 1);
}

// ---------------- output f_hat (straight-through) ----------------
__global__ void k_out(const float* __restrict__ fin, float* __restrict__ out) {
    int e = blockIdx.x * 256 + threadIdx.x;
    if (e < NTOT) out[e] = fin[e] + (g_fhat[e] - fin[e]);
}

// ---------------- loss + perplexity scalars ----------------
__global__ void k_final(float* __restrict__ out, int out_size) {
    __shared__ float red[256];
    int tid = threadIdx.x;
    float s = 0.f;
    for (int i = tid; i < NE; i += 256) {
        float p = (float)g_hist[i] * (1.0f / 32768.0f);
        s += p * logf(p + 1e-10f);
    }
    red[tid] = s;
    __syncthreads();
    for (int o = 128; o; o >>= 1) {
        if (tid < o) red[tid] += red[tid + o];
        __syncthreads();
    }
    if (tid == 0) {
        if (out_size > NTOT)     out[NTOT]     = 1.25f * g_losssum / (10.0f * (float)NTOT);
        if (out_size > NTOT + 1) out[NTOT + 1] = expf(-red[0]);
    }
}

// ---------------- host launcher (graph-capturable, allocation-free) ----------------
extern "C" void kernel_launch(void* const* d_in, const int* in_sizes, int n_in,
                              void* d_out, int out_size) {
    const int pns[10]  = {1, 2, 3, 4, 5, 6, 8, 10, 13, 16};
    const int Sarr[10] = {32, 16, 8, 8, 8, 8, 4, 4, 2, 2};

    // Bind inputs by element count (robust to harness input ordering)
    const float* f_input  = nullptr;
    const float* codebook = nullptr;
    const float* phi_w    = nullptr;
    const float* phi_b    = nullptr;
    for (int i = 0; i < n_in; i++) {
        switch (in_sizes[i]) {
            case 1048576: f_input  = (const float*)d_in[i]; break;
            case 131072:  codebook = (const float*)d_in[i]; break;
            case 36864:   phi_w    = (const float*)d_in[i]; break;
            case 128:     phi_b    = (const float*)d_in[i]; break;
            default: break;
        }
    }
    float* out = (float*)d_out;

    void *p_fhat, *p_frest, *p_loss, *p_hist, *p_x, *p_h0, *p_hup;
    cudaGetSymbolAddress(&p_fhat,  g_fhat);
    cudaGetSymbolAddress(&p_frest, g_frest);
    cudaGetSymbolAddress(&p_loss,  g_losssum);
    cudaGetSymbolAddress(&p_hist,  g_hist);
    cudaGetSymbolAddress(&p_x,     g_x);
    cudaGetSymbolAddress(&p_h0,    g_h0);
    cudaGetSymbolAddress(&p_hup,   g_hup);

    cudaMemsetAsync(p_fhat, 0, sizeof(float) * NTOT);
    cudaMemsetAsync(p_loss, 0, sizeof(float));
    cudaMemsetAsync(p_hist, 0, sizeof(int) * NE);
    cudaMemcpyAsync(p_frest, f_input, sizeof(float) * NTOT, cudaMemcpyDeviceToDevice);

    const int phiSmem = (8192 + 12288 + 32) * sizeof(float);
    cudaFuncSetAttribute(k_phi, cudaFuncAttributeMaxDynamicSharedMemorySize, phiSmem);

    k_taps<<<1, 256>>>();
    k_cbnorm<<<NE / 8, 256>>>(codebook);

    for (int si = 0; si < 10; si++) {
        int pn = pns[si], pp = pn * pn, T = BB * pp;
        const float* xin;
        if (si < 9) {
            int tot = BB * CCH * pp;
            k_down<<<(tot + 255) / 256, 256>>>((const float*)p_frest, (float*)p_x, pn);
            xin = (const float*)p_x;
        } else {
            xin = (const float*)p_frest;
        }
        int bx = (T + 255) / 256;
        int S = Sarr[si], cs = NE / S;
        dim3 g(bx, S);
        k_argmax<<<g, 256>>>(xin, pp, T, cs);

        int tot2 = T * CCH;
        k_merge<<<(tot2 + 255) / 256, 256>>>(codebook, pp, T, S, (si == 9) ? 1 : 0);

        const float* hin;
        if (si < 9) {
            k_up<<<NTOT / 256, 256>>>(pn, si);
            hin = (const float*)p_hup;
        } else {
            hin = (const float*)p_h0;
        }
        k_phi<<<BB, 256, phiSmem>>>(hin, phi_w, phi_b, f_input, si);
    }

    k_hist<<<BB, 256>>>();
    k_out<<<NTOT / 256, 256>>>(f_input, out);
    k_final<<<1, 256>>>(out, out_size);
}

// round 15
// speedup vs baseline: 1.0001x; 1.0001x over previous
#include <cuda_runtime.h>
#include <math.h>

#define BB   128
#define CCH  32
#define HW2  256     // 16*16
#define NE   4096
#define NTOT (BB*CCH*HW2)   // 1048576

// ---------------- device scratch (no allocations allowed) ----------------
__device__ float g_frest[NTOT];
__device__ float g_fhat[NTOT];
__device__ float g_x[BB*CCH*169];          // max downsampled (pn=13)
__device__ float g_h0[NTOT];               // codebook gather output
__device__ float g_hup[NTOT];              // upsampled h
__device__ __align__(16) float g_cbn[NE*CCH];
__device__ float g_pmax[140000];
__device__ int   g_pidx[140000];
__device__ int   g_idx[BB*256];
__device__ float g_losssum;
__device__ int   g_hist[NE];
__device__ float g_tw[9][16][4];
__device__ int   g_tj[9][16][4];
__device__ int   g_phik[10];               // device-computed phi schedule

__constant__ int c_pns9[9] = {1,2,3,4,5,6,8,10,13};

// ---------------- f32x2 helpers ----------------
__device__ __forceinline__ unsigned long long pack2f(float a, float b) {
    unsigned long long r;
    asm("mov.b64 %0, {%1, %2};" : "=l"(r) : "f"(a), "f"(b));
    return r;
}
__device__ __forceinline__ void fma2(unsigned long long& acc, unsigned long long a, unsigned long long b) {
    asm("fma.rn.f32x2 %0, %1, %2, %0;" : "+l"(acc) : "l"(a), "l"(b));
}
__device__ __forceinline__ void unpack2f(unsigned long long v, float& x, float& y) {
    asm("mov.b64 {%0, %1}, %2;" : "=f"(x), "=f"(y) : "l"(v));
}

// ---------------- init: bicubic taps + phi tick schedule ----------------
__global__ void k_taps() {
    int i = threadIdx.x;
    if (i == 0) {
        // Bit-exact replication of:
        //   ticks = np.linspace(1/12, 1-1/12, 4)
        //   PHI_IDX[si] = argmin |ticks - si/9|   (first min on ties)
        double start = 1.0 / 12.0;
        double stop  = 1.0 - 1.0 / 12.0;
        double step  = (stop - start) / 3.0;
        double ticks[4];
        ticks[0] = start;
        ticks[1] = 1.0 * step + start;
        ticks[2] = 2.0 * step + start;   // 2*step exact (pow2 mul) -> FMA-safe
        ticks[3] = stop;
        for (int si = 0; si < 10; si++) {
            double v = (double)si / 9.0;
            int k = 0;
            double bd = fabs(ticks[0] - v);
            for (int j = 1; j < 4; j++) {
                double d = fabs(ticks[j] - v);
                if (d < bd) { bd = d; k = j; }
            }
            g_phik[si] = k;
        }
    }
    if (i >= 144) return;
    int si = i / 16, oi = i % 16;
    int pn = c_pns9[si];
    double src = (oi + 0.5) * (double)pn / 16.0 - 0.5;
    double fl = floor(src);
    int i0 = (int)fl;
    double f = src - fl;
    const double a = -0.75;
    #pragma unroll
    for (int off = -1; off <= 2; off++) {
        double t = fabs(f - (double)off);
        double w;
        if (t <= 1.0)      w = ((a + 2.0) * t - (a + 3.0)) * t * t + 1.0;
        else if (t < 2.0)  w = (((t - 5.0) * t + 8.0) * t - 4.0) * a;
        else               w = 0.0;
        int j = i0 + off;
        if (j < 0) j = 0;
        if (j > pn - 1) j = pn - 1;
        g_tw[si][oi][off + 1] = (float)w;
        g_tj[si][oi][off + 1] = j;
    }
}

// ---------------- codebook row-normalize ----------------
__global__ void k_cbnorm(const float* __restrict__ cb) {
    int row  = blockIdx.x * 8 + (threadIdx.x >> 5);
    int lane = threadIdx.x & 31;
    float v = cb[row * CCH + lane];
    float ss = v * v;
    #pragma unroll
    for (int o = 16; o; o >>= 1) ss += __shfl_xor_sync(0xffffffffu, ss, o);
    float nrm = fmaxf(sqrtf(ss), 1e-12f);
    g_cbn[row * CCH + lane] = v / nrm;
}

// ---------------- area downsample (f_rest -> x) ----------------
__global__ void k_down(const float* __restrict__ in, float* __restrict__ out, int pn) {
    int e = blockIdx.x * 256 + threadIdx.x;
    int pp = pn * pn;
    int tot = BB * CCH * pp;
    if (e >= tot) return;
    int p  = e % pn;
    int o  = (e / pn) % pn;
    int bc = e / pp;
    int s0 = (o * 16) / pn,       e0 = ((o + 1) * 16 + pn - 1) / pn;
    int s1 = (p * 16) / pn,       e1 = ((p + 1) * 16 + pn - 1) / pn;
    const float* base = in + (size_t)bc * HW2;
    float sum = 0.f;
    for (int y = s0; y < e0; y++)
        for (int x = s1; x < e1; x++)
            sum += base[y * 16 + x];
    out[e] = sum / (float)((e0 - s0) * (e1 - s1));
}

// ---------------- cosine argmax (partial over a code slice) ----------------
__global__ void k_argmax(const float* __restrict__ x, int pp, int T, int cs) {
    __shared__ __align__(16) float sh[128 * 32];
    int slice  = blockIdx.y;
    int c0base = slice * cs;
    int t = blockIdx.x * 256 + threadIdx.x;
    bool valid = (t < T);
    unsigned long long xp[16];
    if (valid) {
        int b = t / pp, r = t - b * pp;
        const float* bp = x + (size_t)b * CCH * pp + r;
        #pragma unroll
        for (int q = 0; q < 16; q++)
            xp[q] = pack2f(bp[(2 * q) * pp], bp[(2 * q + 1) * pp]);
    }
    float best = -1e30f;
    int bi = 0;
    for (int tile = 0; tile < cs; tile += 128) {
        const float4* src = (const float4*)(g_cbn + (size_t)(c0base + tile) * CCH);
        float4* dst = (float4*)sh;
        #pragma unroll
        for (int q = 0; q < 4; q++)
            dst[threadIdx.x + q * 256] = src[threadIdx.x + q * 256];
        __syncthreads();
        if (valid) {
            #pragma unroll 4
            for (int c = 0; c < 128; c += 2) {
                const longlong2* r0 = (const longlong2*)(sh + c * 32);
                const longlong2* r1 = (const longlong2*)(sh + c * 32 + 32);
                unsigned long long a0 = 0ull, a1 = 0ull;
                #pragma unroll
                for (int q = 0; q < 8; q++) {
                    longlong2 v0 = r0[q];
                    longlong2 v1 = r1[q];
                    fma2(a0, xp[2 * q],     (unsigned long long)v0.x);
                    fma2(a0, xp[2 * q + 1], (unsigned long long)v0.y);
                    fma2(a1, xp[2 * q],     (unsigned long long)v1.x);
                    fma2(a1, xp[2 * q + 1], (unsigned long long)v1.y);
                }
                float s0x, s0y, s1x, s1y;
                unpack2f(a0, s0x, s0y);
                unpack2f(a1, s1x, s1y);
                float s0 = s0x + s0y, s1 = s1x + s1y;
                if (s0 > best) { best = s0; bi = c0base + tile + c; }
                if (s1 > best) { best = s1; bi = c0base + tile + c + 1; }
            }
        }
        __syncthreads();
    }
    if (valid) {
        g_pmax[(size_t)slice * T + t] = best;
        g_pidx[(size_t)slice * T + t] = bi;
    }
}

// ---------------- merge partials + gather codebook -> h0 ----------------
__global__ void k_merge(const float* __restrict__ cb, int pp, int T, int S, int last) {
    int e = blockIdx.x * 256 + threadIdx.x;
    if (e >= T * CCH) return;
    int r = e % pp;
    int c = (e / pp) & 31;
    int b = e / (CCH * pp);
    int t = b * pp + r;
    float best = -1e30f;
    int bi = 0;
    for (int s = 0; s < S; s++) {
        float v = g_pmax[(size_t)s * T + t];
        if (v > best) { best = v; bi = g_pidx[(size_t)s * T + t]; }
    }
    g_h0[e] = cb[bi * CCH + c];
    if (last && c == 0) g_idx[t] = bi;
}

// ---------------- bicubic upsample (h0 -> hup) ----------------
__global__ void k_up(int pn, int si) {
    int e = blockIdx.x * 256 + threadIdx.x;   // < NTOT
    int x = e & 15, y = (e >> 4) & 15, bc = e >> 8;
    const float* base = g_h0 + (size_t)bc * pn * pn;
    float acc = 0.f;
    #pragma unroll
    for (int a = 0; a < 4; a++) {
        int jy = g_tj[si][y][a];
        float wy = g_tw[si][y][a];
        float rs = 0.f;
        #pragma unroll
        for (int bq = 0; bq < 4; bq++)
            rs += g_tw[si][x][bq] * base[jy * pn + g_tj[si][x][bq]];
        acc += wy * rs;
    }
    g_hup[e] = acc;
}

// ---------------- fused conv3x3 + phi-blend + fhat/frest update + loss ----------------
__global__ void k_phi(const float* __restrict__ h, const float* __restrict__ pw,
                      const float* __restrict__ pb, const float* __restrict__ fin, int si) {
    extern __shared__ float sm[];
    float* s_in = sm;                 // 8192 floats
    float* s_w  = sm + 8192;          // 32*32*12 = 12288 floats (padded per (co,ci))
    float* s_b  = sm + 8192 + 12288;  // 32 floats
    __shared__ float s_red[256];
    int b = blockIdx.x, tid = threadIdx.x;
    int kphi = g_phik[si];

    const float* hb = h + (size_t)b * 8192;
    for (int i = tid; i < 8192; i += 256) s_in[i] = hb[i];
    const float* wb = pw + (size_t)kphi * 9216;
    for (int i = tid; i < 9216; i += 256) {
        int oc = i / 9, k = i - oc * 9;
        s_w[oc * 12 + k] = wb[i];
    }
    if (tid < 32) s_b[tid] = pb[kphi * 32 + tid];
    __syncthreads();

    int y = tid >> 4, x = tid & 15;
    float acc[32];
    #pragma unroll
    for (int co = 0; co < 32; co++) acc[co] = 0.f;

    #pragma unroll 1
    for (int ci = 0; ci < 32; ci++) {
        float n[9];
        #pragma unroll
        for (int ky = 0; ky < 3; ky++)
            #pragma unroll
            for (int kx = 0; kx < 3; kx++) {
                int yy = y + ky - 1, xx = x + kx - 1;
                n[ky * 3 + kx] = (yy >= 0 && yy < 16 && xx >= 0 && xx < 16)
                               ? s_in[ci * 256 + yy * 16 + xx] : 0.f;
            }
        #pragma unroll
        for (int co = 0; co < 32; co++) {
            const float* wp = s_w + (co * 32 + ci) * 12;
            float4 w0 = *(const float4*)wp;
            float4 w1 = *(const float4*)(wp + 4);
            float w8 = wp[8];
            acc[co] += n[0]*w0.x + n[1]*w0.y + n[2]*w0.z + n[3]*w0.w
                     + n[4]*w1.x + n[5]*w1.y + n[6]*w1.z + n[7]*w1.w + n[8]*w8;
        }
    }

    float ls = 0.f;
    size_t base = (size_t)b * 8192 + tid;
    #pragma unroll
    for (int co = 0; co < 32; co++) {
        size_t e = base + (size_t)co * 256;
        float hv = s_in[co * 256 + tid];
        float hp = 0.5f * hv + 0.5f * (acc[co] + s_b[co]);
        float fh = g_fhat[e] + hp;
        g_fhat[e] = fh;
        g_frest[e] = g_frest[e] - hp;
        float d = fh - fin[e];
        ls += d * d;
    }
    s_red[tid] = ls;
    __syncthreads();
    for (int o = 128; o; o >>= 1) {
        if (tid < o) s_red[tid] += s_red[tid + o];
        __syncthreads();
    }
    if (tid == 0) atomicAdd(&g_losssum, s_red[0]);
}

// ---------------- histogram of last-scale indices ----------------
__global__ void k_hist() {
    int e = blockIdx.x * 256 + threadIdx.x;
    if (e < BB * 256) atomicAdd(&g_hist[g_idx[e]], 1);
}

// ---------------- output f_hat (straight-through) ----------------
__global__ void k_out(const float* __restrict__ fin, float* __restrict__ out) {
    int e = blockIdx.x * 256 + threadIdx.x;
    if (e < NTOT) out[e] = fin[e] + (g_fhat[e] - fin[e]);
}

// ---------------- loss + perplexity scalars ----------------
__global__ void k_final(float* __restrict__ out, int out_size) {
    __shared__ float red[256];
    int tid = threadIdx.x;
    float s = 0.f;
    for (int i = tid; i < NE; i += 256) {
        float p = (float)g_hist[i] * (1.0f / 32768.0f);
        s += p * logf(p + 1e-10f);
    }
    red[tid] = s;
    __syncthreads();
    for (int o = 128; o; o >>= 1) {
        if (tid < o) red[tid] += red[tid + o];
        __syncthreads();
    }
    if (tid == 0) {
        if (out_size > NTOT)     out[NTOT]     = 1.25f * g_losssum / (10.0f * (float)NTOT);
        if (out_size > NTOT + 1) out[NTOT + 1] = expf(-red[0]);
    }
}

// ---------------- host launcher (graph-capturable, allocation-free) ----------------
extern "C" void kernel_launch(void* const* d_in, const int* in_sizes, int n_in,
                              void* d_out, int out_size) {
    const int pns[10]  = {1, 2, 3, 4, 5, 6, 8, 10, 13, 16};
    const int Sarr[10] = {32, 16, 8, 8, 8, 8, 4, 4, 2, 2};

    // Bind inputs by element count (robust to harness input ordering)
    const float* f_input  = nullptr;
    const float* codebook = nullptr;
    const float* phi_w    = nullptr;
    const float* phi_b    = nullptr;
    for (int i = 0; i < n_in; i++) {
        switch (in_sizes[i]) {
            case 1048576: f_input  = (const float*)d_in[i]; break;
            case 131072:  codebook = (const float*)d_in[i]; break;
            case 36864:   phi_w    = (const float*)d_in[i]; break;
            case 128:     phi_b    = (const float*)d_in[i]; break;
            default: break;
        }
    }
    float* out = (float*)d_out;

    void *p_fhat, *p_frest, *p_loss, *p_hist, *p_x, *p_h0, *p_hup;
    cudaGetSymbolAddress(&p_fhat,  g_fhat);
    cudaGetSymbolAddress(&p_frest, g_frest);
    cudaGetSymbolAddress(&p_loss,  g_losssum);
    cudaGetSymbolAddress(&p_hist,  g_hist);
    cudaGetSymbolAddress(&p_x,     g_x);
    cudaGetSymbolAddress(&p_h0,    g_h0);
    cudaGetSymbolAddress(&p_hup,   g_hup);

    cudaMemsetAsync(p_fhat, 0, sizeof(float) * NTOT);
    cudaMemsetAsync(p_loss, 0, sizeof(float));
    cudaMemsetAsync(p_hist, 0, sizeof(int) * NE);
    cudaMemcpyAsync(p_frest, f_input, sizeof(float) * NTOT, cudaMemcpyDeviceToDevice);

    const int phiSmem = (8192 + 12288 + 32) * sizeof(float);
    cudaFuncSetAttribute(k_phi, cudaFuncAttributeMaxDynamicSharedMemorySize, phiSmem);

    k_taps<<<1, 256>>>();
    k_cbnorm<<<NE / 8, 256>>>(codebook);

    for (int si = 0; si < 10; si++) {
        int pn = pns[si], pp = pn * pn, T = BB * pp;
        const float* xin;
        if (si < 9) {
            int tot = BB * CCH * pp;
            k_down<<<(tot + 255) / 256, 256>>>((const float*)p_frest, (float*)p_x, pn);
            xin = (const float*)p_x;
        } else {
            xin = (const float*)p_frest;
        }
        int bx = (T + 255) / 256;
        int S = Sarr[si], cs = NE / S;
        dim3 g(bx, S);
        k_argmax<<<g, 256>>>(xin, pp, T, cs);

        int tot2 = T * CCH;
        k_merge<<<(tot2 + 255) / 256, 256>>>(codebook, pp, T, S, (si == 9) ? 1 : 0);

        const float* hin;
        if (si < 9) {
            k_up<<<NTOT / 256, 256>>>(pn, si);
            hin = (const float*)p_hup;
        } else {
            hin = (const float*)p_h0;
        }
        k_phi<<<BB, 256, phiSmem>>>(hin, phi_w, phi_b, f_input, si);
    }

    k_hist<<<BB, 256>>>();
    k_out<<<NTOT / 256, 256>>>(f_input, out);
    k_final<<<1, 256>>>(out, out_size);
}

// round 16
// speedup vs baseline: 1.2578x; 1.2576x over previous
#include <cuda_runtime.h>
#include <math.h>

#define BB   128
#define CCH  32
#define HW2  256     // 16*16
#define NE   4096
#define NTOT (BB*CCH*HW2)   // 1048576

// ---------------- device scratch (no allocations allowed) ----------------
__device__ float g_frest[NTOT];
__device__ float g_fhat[NTOT];
__device__ float g_x[BB*CCH*169];          // downsampled input for current scale
__device__ __align__(16) float g_cbn[NE*CCH];
__device__ float g_pmax[140000];
__device__ int   g_pidx[140000];
__device__ float g_losssum;
__device__ int   g_hist[NE];
__device__ float g_tw[9][16][4];
__device__ int   g_tj[9][16][4];
__device__ int   g_phik[10];               // device-computed phi schedule

__constant__ int c_pns9[9] = {1,2,3,4,5,6,8,10,13};

// ---------------- f32x2 helpers ----------------
__device__ __forceinline__ unsigned long long pack2f(float a, float b) {
    unsigned long long r;
    asm("mov.b64 %0, {%1, %2};" : "=l"(r) : "f"(a), "f"(b));
    return r;
}
__device__ __forceinline__ void fma2(unsigned long long& acc, unsigned long long a, unsigned long long b) {
    asm("fma.rn.f32x2 %0, %1, %2, %0;" : "+l"(acc) : "l"(a), "l"(b));
}
__device__ __forceinline__ void unpack2f(unsigned long long v, float& x, float& y) {
    asm("mov.b64 {%0, %1}, %2;" : "=f"(x), "=f"(y) : "l"(v));
}

// ---------------- init: bicubic taps + phi tick schedule ----------------
__global__ void k_taps() {
    int i = threadIdx.x;
    if (i == 0) {
        // Bit-exact replication of np.linspace(1/12, 1-1/12, 4) + first-min argmin
        double start = 1.0 / 12.0;
        double stop  = 1.0 - 1.0 / 12.0;
        double step  = (stop - start) / 3.0;
        double ticks[4];
        ticks[0] = start;
        ticks[1] = 1.0 * step + start;
        ticks[2] = 2.0 * step + start;
        ticks[3] = stop;
        for (int si = 0; si < 10; si++) {
            double v = (double)si / 9.0;
            int k = 0;
            double bd = fabs(ticks[0] - v);
            for (int j = 1; j < 4; j++) {
                double d = fabs(ticks[j] - v);
                if (d < bd) { bd = d; k = j; }
            }
            g_phik[si] = k;
        }
    }
    if (i >= 144) return;
    int si = i / 16, oi = i % 16;
    int pn = c_pns9[si];
    double src = (oi + 0.5) * (double)pn / 16.0 - 0.5;
    double fl = floor(src);
    int i0 = (int)fl;
    double f = src - fl;
    const double a = -0.75;
    #pragma unroll
    for (int off = -1; off <= 2; off++) {
        double t = fabs(f - (double)off);
        double w;
        if (t <= 1.0)      w = ((a + 2.0) * t - (a + 3.0)) * t * t + 1.0;
        else if (t < 2.0)  w = (((t - 5.0) * t + 8.0) * t - 4.0) * a;
        else               w = 0.0;
        int j = i0 + off;
        if (j < 0) j = 0;
        if (j > pn - 1) j = pn - 1;
        g_tw[si][oi][off + 1] = (float)w;
        g_tj[si][oi][off + 1] = j;
    }
}

// ---------------- codebook row-normalize ----------------
__global__ void k_cbnorm(const float* __restrict__ cb) {
    int row  = blockIdx.x * 8 + (threadIdx.x >> 5);
    int lane = threadIdx.x & 31;
    float v = cb[row * CCH + lane];
    float ss = v * v;
    #pragma unroll
    for (int o = 16; o; o >>= 1) ss += __shfl_xor_sync(0xffffffffu, ss, o);
    float nrm = fmaxf(sqrtf(ss), 1e-12f);
    g_cbn[row * CCH + lane] = v / nrm;
}

// ---------------- area downsample for scale 0 only (from f_input) ----------------
__global__ void k_down0(const float* __restrict__ in, float* __restrict__ out, int pn) {
    int e = blockIdx.x * 256 + threadIdx.x;
    int pp = pn * pn;
    int tot = BB * CCH * pp;
    if (e >= tot) return;
    int p  = e % pn;
    int o  = (e / pn) % pn;
    int bc = e / pp;
    int s0 = (o * 16) / pn,       e0 = ((o + 1) * 16 + pn - 1) / pn;
    int s1 = (p * 16) / pn,       e1 = ((p + 1) * 16 + pn - 1) / pn;
    const float* base = in + (size_t)bc * HW2;
    float sum = 0.f;
    for (int y = s0; y < e0; y++)
        for (int x = s1; x < e1; x++)
            sum += base[y * 16 + x];
    out[e] = sum / (float)((e0 - s0) * (e1 - s1));
}

// ---------------- cosine argmax (partial over a code slice) ----------------
__global__ void k_argmax(const float* __restrict__ x, int pp, int T, int cs) {
    __shared__ __align__(16) float sh[128 * 32];
    int slice  = blockIdx.y;
    int c0base = slice * cs;
    int t = blockIdx.x * 256 + threadIdx.x;
    bool valid = (t < T);
    unsigned long long xp[16];
    if (valid) {
        int b = t / pp, r = t - b * pp;
        const float* bp = x + (size_t)b * CCH * pp + r;
        #pragma unroll
        for (int q = 0; q < 16; q++)
            xp[q] = pack2f(bp[(2 * q) * pp], bp[(2 * q + 1) * pp]);
    }
    float best = -1e30f;
    int bi = 0;
    for (int tile = 0; tile < cs; tile += 128) {
        const float4* src = (const float4*)(g_cbn + (size_t)(c0base + tile) * CCH);
        float4* dst = (float4*)sh;
        #pragma unroll
        for (int q = 0; q < 4; q++)
            dst[threadIdx.x + q * 256] = src[threadIdx.x + q * 256];
        __syncthreads();
        if (valid) {
            #pragma unroll 4
            for (int c = 0; c < 128; c += 2) {
                const longlong2* r0 = (const longlong2*)(sh + c * 32);
                const longlong2* r1 = (const longlong2*)(sh + c * 32 + 32);
                unsigned long long a0 = 0ull, a1 = 0ull;
                #pragma unroll
                for (int q = 0; q < 8; q++) {
                    longlong2 v0 = r0[q];
                    longlong2 v1 = r1[q];
                    fma2(a0, xp[2 * q],     (unsigned long long)v0.x);
                    fma2(a0, xp[2 * q + 1], (unsigned long long)v0.y);
                    fma2(a1, xp[2 * q],     (unsigned long long)v1.x);
                    fma2(a1, xp[2 * q + 1], (unsigned long long)v1.y);
                }
                float s0x, s0y, s1x, s1y;
                unpack2f(a0, s0x, s0y);
                unpack2f(a1, s1x, s1y);
                float s0 = s0x + s0y, s1 = s1x + s1y;
                if (s0 > best) { best = s0; bi = c0base + tile + c; }
                if (s1 > best) { best = s1; bi = c0base + tile + c + 1; }
            }
        }
        __syncthreads();
    }
    if (valid) {
        g_pmax[(size_t)slice * T + t] = best;
        g_pidx[(size_t)slice * T + t] = bi;
    }
}

// ---------------- fused: merge + gather + upsample + conv(f32x2) + blend
//                  + fhat/frest update + loss + downsample(next) + hist + out
// one block per image b; 256 threads.
// shared layout (floats): s_in[8192] | s_w[10240] | s_b[32] | s_h0[8192] | s_idx(int)[256]
__global__ void k_phi_fused(const float* __restrict__ cb, const float* __restrict__ pw,
                            const float* __restrict__ pb, const float* __restrict__ fin,
                            float* __restrict__ out,
                            int si, int pn, int S, int T, int next_pn, int last) {
    extern __shared__ float sm[];
    float* s_in = sm;                         // 8192
    float* s_w  = sm + 8192;                  // 10240 (16 co-pairs x 32 ci x 10 ull, padded)
    float* s_b  = sm + 8192 + 10240;          // 32
    float* s_h0 = sm + 8192 + 10240 + 32;     // 8192
    int*   s_idx = (int*)(sm + 8192 + 10240 + 32 + 8192);  // 256
    __shared__ float s_red[256];

    int b = blockIdx.x, tid = threadIdx.x;
    int pp = pn * pn;
    int kphi = g_phik[si];

    // 1) merge partial argmaxes for this block's tokens (first-max tie-break, slice order)
    if (tid < pp) {
        int t = b * pp + tid;
        float best = -1e30f;
        int bi = 0;
        for (int s = 0; s < S; s++) {
            float v = g_pmax[(size_t)s * T + t];
            if (v > best) { best = v; bi = g_pidx[(size_t)s * T + t]; }
        }
        s_idx[tid] = bi;
        if (last) atomicAdd(&g_hist[bi], 1);
    }

    // 2) stage weights (co-pair packed, stride 20 floats per (co2,ci)) + bias
    const float* wb = pw + (size_t)kphi * 9216;
    for (int i = tid; i < 9216; i += 256) {
        int co = i / 288, rem = i - co * 288;
        int ci = rem / 9, k = rem - ci * 9;
        s_w[((co >> 1) * 32 + ci) * 20 + k * 2 + (co & 1)] = wb[i];
    }
    if (tid < 32) s_b[tid] = pb[kphi * 32 + tid];
    __syncthreads();

    // 3) gather codebook rows (coalesced read, layout [c*pp + r]); last scale writes s_in directly
    float* gdst = last ? s_in : s_h0;
    for (int i = tid; i < pp * 32; i += 256) {
        int c = i & 31, r = i >> 5;
        gdst[c * pp + r] = cb[(size_t)s_idx[r] * 32 + c];
    }
    __syncthreads();

    // 4) bicubic upsample h0 -> s_in (non-last scales)
    if (!last) {
        for (int e = tid; e < 8192; e += 256) {
            int x = e & 15, y = (e >> 4) & 15, c = e >> 8;
            const float* base = s_h0 + c * pp;
            float acc = 0.f;
            #pragma unroll
            for (int a = 0; a < 4; a++) {
                int jy = g_tj[si][y][a];
                float wy = g_tw[si][y][a];
                float rs = 0.f;
                #pragma unroll
                for (int bq = 0; bq < 4; bq++)
                    rs += g_tw[si][x][bq] * base[jy * pn + g_tj[si][x][bq]];
                acc += wy * rs;
            }
            s_in[e] = acc;
        }
        __syncthreads();
    }

    // 5) conv3x3 over 32 in-ch, 32 out-ch packed as 16 f32x2 accumulators
    int y = tid >> 4, x = tid & 15;
    unsigned long long acc2[16];
    #pragma unroll
    for (int q = 0; q < 16; q++) acc2[q] = 0ull;

    #pragma unroll 1
    for (int ci = 0; ci < 32; ci++) {
        unsigned long long n2[9];
        #pragma unroll
        for (int ky = 0; ky < 3; ky++)
            #pragma unroll
            for (int kx = 0; kx < 3; kx++) {
                int yy = y + ky - 1, xx = x + kx - 1;
                float nv = (yy >= 0 && yy < 16 && xx >= 0 && xx < 16)
                         ? s_in[ci * 256 + yy * 16 + xx] : 0.f;
                n2[ky * 3 + kx] = pack2f(nv, nv);
            }
        #pragma unroll
        for (int co2 = 0; co2 < 16; co2++) {
            const ulonglong2* wp = (const ulonglong2*)(s_w + (co2 * 32 + ci) * 20);
            ulonglong2 w01 = wp[0], w23 = wp[1], w45 = wp[2], w67 = wp[3];
            unsigned long long w8 = *((const unsigned long long*)(s_w + (co2 * 32 + ci) * 20 + 16));
            fma2(acc2[co2], n2[0], w01.x);
            fma2(acc2[co2], n2[1], w01.y);
            fma2(acc2[co2], n2[2], w23.x);
            fma2(acc2[co2], n2[3], w23.y);
            fma2(acc2[co2], n2[4], w45.x);
            fma2(acc2[co2], n2[5], w45.y);
            fma2(acc2[co2], n2[6], w67.x);
            fma2(acc2[co2], n2[7], w67.y);
            fma2(acc2[co2], n2[8], w8);
        }
    }

    // 6) blend + fhat/frest update + loss; overwrite s_in in place with new frest
    float ls = 0.f;
    size_t base = (size_t)b * 8192 + tid;
    #pragma unroll
    for (int co2 = 0; co2 < 16; co2++) {
        float c0, c1;
        unpack2f(acc2[co2], c0, c1);
        #pragma unroll
        for (int half = 0; half < 2; half++) {
            int co = co2 * 2 + half;
            float cv = half ? c1 : c0;
            size_t e = base + (size_t)co * 256;
            float hv = s_in[co * 256 + tid];
            float hp = 0.5f * hv + 0.5f * (cv + s_b[co]);
            float fh = g_fhat[e] + hp;
            float fi = fin[e];
            float d = fh - fi;
            ls += d * d;
            if (last) {
                out[e] = fi + (fh - fi);
            } else {
                g_fhat[e] = fh;
                float nr = g_frest[e] - hp;
                g_frest[e] = nr;
                s_in[co * 256 + tid] = nr;     // own element only: race-free
            }
        }
    }
    s_red[tid] = ls;
    __syncthreads();
    for (int o = 128; o; o >>= 1) {
        if (tid < o) s_red[tid] += s_red[tid + o];
        __syncthreads();
    }
    if (tid == 0) atomicAdd(&g_losssum, s_red[0]);

    // 7) area-downsample new frest -> g_x for next scale (layout [(b*32+c)*pp' + r'])
    if (next_pn > 0) {
        int npp = next_pn * next_pn;
        for (int i = tid; i < 32 * npp; i += 256) {
            int c = i / npp, rr = i - c * npp;
            int oy = rr / next_pn, ox = rr - oy * next_pn;
            int s0 = (oy * 16) / next_pn, e0 = ((oy + 1) * 16 + next_pn - 1) / next_pn;
            int s1 = (ox * 16) / next_pn, e1 = ((ox + 1) * 16 + next_pn - 1) / next_pn;
            const float* bp = s_in + c * 256;
            float sum = 0.f;
            for (int yy = s0; yy < e0; yy++)
                for (int xx = s1; xx < e1; xx++)
                    sum += bp[yy * 16 + xx];
            g_x[((size_t)(b * 32) + c) * npp + rr] = sum / (float)((e0 - s0) * (e1 - s1));
        }
    }
}

// ---------------- loss + perplexity scalars ----------------
__global__ void k_final(float* __restrict__ out, int out_size) {
    __shared__ float red[256];
    int tid = threadIdx.x;
    float s = 0.f;
    for (int i = tid; i < NE; i += 256) {
        float p = (float)g_hist[i] * (1.0f / 32768.0f);
        s += p * logf(p + 1e-10f);
    }
    red[tid] = s;
    __syncthreads();
    for (int o = 128; o; o >>= 1) {
        if (tid < o) red[tid] += red[tid + o];
        __syncthreads();
    }
    if (tid == 0) {
        if (out_size > NTOT)     out[NTOT]     = 1.25f * g_losssum / (10.0f * (float)NTOT);
        if (out_size > NTOT + 1) out[NTOT + 1] = expf(-red[0]);
    }
}

// ---------------- host launcher (graph-capturable, allocation-free) ----------------
extern "C" void kernel_launch(void* const* d_in, const int* in_sizes, int n_in,
                              void* d_out, int out_size) {
    const int pns[10]  = {1, 2, 3, 4, 5, 6, 8, 10, 13, 16};
    const int Sarr[10] = {32, 32, 32, 32, 16, 16, 8, 8, 4, 4};

    // Bind inputs by element count (robust to harness input ordering)
    const float* f_input  = nullptr;
    const float* codebook = nullptr;
    const float* phi_w    = nullptr;
    const float* phi_b    = nullptr;
    for (int i = 0; i < n_in; i++) {
        switch (in_sizes[i]) {
            case 1048576: f_input  = (const float*)d_in[i]; break;
            case 131072:  codebook = (const float*)d_in[i]; break;
            case 36864:   phi_w    = (const float*)d_in[i]; break;
            case 128:     phi_b    = (const float*)d_in[i]; break;
            default: break;
        }
    }
    float* out = (float*)d_out;

    void *p_fhat, *p_frest, *p_loss, *p_hist, *p_x;
    cudaGetSymbolAddress(&p_fhat,  g_fhat);
    cudaGetSymbolAddress(&p_frest, g_frest);
    cudaGetSymbolAddress(&p_loss,  g_losssum);
    cudaGetSymbolAddress(&p_hist,  g_hist);
    cudaGetSymbolAddress(&p_x,     g_x);

    cudaMemsetAsync(p_fhat, 0, sizeof(float) * NTOT);
    cudaMemsetAsync(p_loss, 0, sizeof(float));
    cudaMemsetAsync(p_hist, 0, sizeof(int) * NE);
    cudaMemcpyAsync(p_frest, f_input, sizeof(float) * NTOT, cudaMemcpyDeviceToDevice);

    const int phiSmem = (8192 + 10240 + 32 + 8192 + 256) * sizeof(float);
    cudaFuncSetAttribute(k_phi_fused, cudaFuncAttributeMaxDynamicSharedMemorySize, phiSmem);

    k_taps<<<1, 256>>>();
    k_cbnorm<<<NE / 8, 256>>>(codebook);
    k_down0<<<(BB * CCH + 255) / 256, 256>>>(f_input, (float*)p_x, 1);   // pn=1: 4096 elems

    for (int si = 0; si < 10; si++) {
        int pn = pns[si], pp = pn * pn, T = BB * pp;
        const float* xin = (si == 9) ? (const float*)p_frest : (const float*)p_x;
        int bx = (T + 255) / 256;
        int S = Sarr[si], cs = NE / S;
        dim3 g(bx, S);
        k_argmax<<<g, 256>>>(xin, pp, T, cs);

        int next_pn = (si < 8) ? pns[si + 1] : 0;   // si=8 -> next scale reads frest directly
        int last = (si == 9) ? 1 : 0;
        k_phi_fused<<<BB, 256, phiSmem>>>(codebook, phi_w, phi_b, f_input, out,
                                          si, pn, S, T, next_pn, last);
    }

    k_final<<<1, 256>>>(out, out_size);
}